// round 6
// baseline (speedup 1.0000x reference)
#include <cuda_runtime.h>
#include <cuda_bf16.h>
#include <math.h>
#include <stdint.h>

#define Bv  8
#define Tv  32
#define Nv  500
#define Fv  64
#define Hv  128
#define Ev  8000
#define BT  256            // B*T
#define BTN 128000         // B*T*N
#define NNZ (Ev + Nv)

// ---------------- scratch (static device globals: allowed) ----------------
__device__ float  g_xf [BTN * Hv];   // x @ W_gcn            (bt, n, h)
__device__ float  g_res[BTN * Hv];   // x @ W_res + b_res    (bt, n, h)
__device__ float  g_hg [BTN * Hv];   // gelu(gcn agg + b)    (bt, n, h)
__device__ float  g_deg [Nv];
__device__ float  g_dinv[Nv];
__device__ int    g_cnt [Nv];
__device__ int    g_rowptr[Nv + 1];
__device__ int    g_fill[Nv];
__device__ float2 g_ev[NNZ];         // {norm, __int_as_float(src)} CSR by dst
__device__ int    g_is64;            // edge_index dtype flag
// W_temp split into mma.sync B-fragment order: [sel(2)][q(24)][f(16)][lane(32)]
__device__ uint2  g_wfrag[2 * 24 * 16 * 32];

// ---------------- helpers ----------------
__device__ __forceinline__ unsigned long long pack2(float lo, float hi) {
    unsigned long long r;
    asm("mov.b64 %0, {%1, %2};" : "=l"(r) : "f"(lo), "f"(hi));
    return r;
}
__device__ __forceinline__ void unpack2(unsigned long long v, float& lo, float& hi) {
    asm("mov.b64 {%0, %1}, %2;" : "=f"(lo), "=f"(hi) : "l"(v));
}
__device__ __forceinline__ void fma2(unsigned long long& d, unsigned long long a,
                                     unsigned long long b) {
    asm("fma.rn.f32x2 %0, %1, %2, %0;" : "+l"(d) : "l"(a), "l"(b));
}
__device__ __forceinline__ float gelu_exact(float x) {
    return 0.5f * x * (1.0f + erff(x * 0.7071067811865476f));
}
__device__ __forceinline__ int load_idx(const void* ei, int i) {
    long long v;
    if (g_is64) v = ((const long long*)ei)[i];
    else        v = ((const int*)ei)[i];
    if (v < 0) v = 0;
    if (v >= Nv) v = Nv - 1;
    return (int)v;
}
__device__ __forceinline__ uint32_t smem_u32(const void* p) {
    uint32_t a;
    asm("{ .reg .u64 t; cvta.to.shared.u64 t, %1; cvt.u32.u64 %0, t; }" : "=r"(a) : "l"(p));
    return a;
}
__device__ __forceinline__ unsigned short bfbits(__nv_bfloat16 h) {
    return *reinterpret_cast<unsigned short*>(&h);
}
// split two floats into packed bf16 hi-words / lo-words
__device__ __forceinline__ void split2(float x0, float x1, uint32_t& hw, uint32_t& lw) {
    __nv_bfloat16 h0 = __float2bfloat16(x0);
    __nv_bfloat16 h1 = __float2bfloat16(x1);
    __nv_bfloat16 l0 = __float2bfloat16(x0 - __bfloat162float(h0));
    __nv_bfloat16 l1 = __float2bfloat16(x1 - __bfloat162float(h1));
    hw = (uint32_t)bfbits(h0) | ((uint32_t)bfbits(h1) << 16);
    lw = (uint32_t)bfbits(l0) | ((uint32_t)bfbits(l1) << 16);
}
__device__ __forceinline__ void ldmx4(uint32_t* a, uint32_t addr) {
    asm volatile("ldmatrix.sync.aligned.m8n8.x4.shared.b16 {%0,%1,%2,%3}, [%4];"
                 : "=r"(a[0]), "=r"(a[1]), "=r"(a[2]), "=r"(a[3]) : "r"(addr));
}
__device__ __forceinline__ void mma16816(float* d, const uint32_t* a, uint2 b) {
    asm volatile(
        "mma.sync.aligned.m16n8k16.row.col.f32.bf16.bf16.f32 "
        "{%0,%1,%2,%3}, {%4,%5,%6,%7}, {%8,%9}, {%0,%1,%2,%3};"
        : "+f"(d[0]), "+f"(d[1]), "+f"(d[2]), "+f"(d[3])
        : "r"(a[0]), "r"(a[1]), "r"(a[2]), "r"(a[3]), "r"(b.x), "r"(b.y));
}

// ---------------- prep kernels ----------------
__global__ void p_detect(const void* __restrict__ ei) {
    if (threadIdx.x != 0) return;
    const long long* p = (const long long*)ei;
    int ok64 = 1;
    for (int i = 0; i < 8; ++i) {
        long long v = p[i];
        if (v < 0 || v >= Nv) ok64 = 0;
    }
    g_is64 = ok64;
}
__global__ void p_init() {
    int i = threadIdx.x;
    if (i < Nv) { g_deg[i] = 0.0f; g_cnt[i] = 0; }
}
__global__ void p_deg(const void* __restrict__ ei, const float* __restrict__ ew) {
    int e = blockIdx.x * blockDim.x + threadIdx.x;
    if (e >= Ev) return;
    int dst = load_idx(ei, Ev + e);
    atomicAdd(&g_deg[dst], ew[e]);
    atomicAdd(&g_cnt[dst], 1);
}
__global__ void p_scan() {
    __shared__ int s[512];
    int tid = threadIdx.x;
    int c = 0;
    if (tid < Nv) {
        float d = g_deg[tid] + 1.0f;
        g_dinv[tid] = 1.0f / sqrtf(d);
        c = g_cnt[tid] + 1;
    }
    s[tid] = c;
    __syncthreads();
    for (int off = 1; off < 512; off <<= 1) {
        int v = (tid >= off) ? s[tid - off] : 0;
        __syncthreads();
        s[tid] += v;
        __syncthreads();
    }
    if (tid < Nv) {
        g_rowptr[tid + 1] = s[tid];
        g_fill[tid] = s[tid] - c;
        if (tid == 0) g_rowptr[0] = 0;
    }
}
__global__ void p_fill(const void* __restrict__ ei, const float* __restrict__ ew) {
    int e = blockIdx.x * blockDim.x + threadIdx.x;
    if (e >= NNZ) return;
    int src, dst; float w;
    if (e < Ev) { src = load_idx(ei, e); dst = load_idx(ei, Ev + e); w = ew[e]; }
    else        { src = dst = e - Ev; w = 1.0f; }
    float v = g_dinv[src] * w * g_dinv[dst];
    int pos = atomicAdd(&g_fill[dst], 1);
    if (pos >= 0 && pos < NNZ)
        g_ev[pos] = make_float2(v, __int_as_float(src));
}
// W_temp -> bf16 hi/lo fragments in mma B order.
// entry (q,f,lane): o = f*8 + lane/4, tap kk = q/8, i window = (q%8)*16,
// reg r: k_local = r*8 + (lane%4)*2
__global__ void p_wsplit(const float* __restrict__ Wt) {
    int idx = blockIdx.x * 128 + threadIdx.x;
    if (idx >= 24 * 16 * 32) return;
    int lane = idx & 31;
    int f = (idx >> 5) & 15;
    int q = idx >> 9;
    int tn = lane >> 2, kp = lane & 3;
    int o = f * 8 + tn;
    int kk = q >> 3;
    int ibase = (q & 7) * 16;
    uint2 hv, lv;
    {
        int i0 = ibase + kp * 2;
        float w0 = Wt[o * 384 + i0 * 3 + kk];
        float w1 = Wt[o * 384 + (i0 + 1) * 3 + kk];
        split2(w0, w1, hv.x, lv.x);
    }
    {
        int i0 = ibase + 8 + kp * 2;
        float w0 = Wt[o * 384 + i0 * 3 + kk];
        float w1 = Wt[o * 384 + (i0 + 1) * 3 + kk];
        split2(w0, w1, hv.y, lv.y);
    }
    g_wfrag[(q * 16 + f) * 32 + lane] = hv;
    g_wfrag[((24 + q) * 16 + f) * 32 + lane] = lv;
}

// ---------------- K2: fused input projections (xf + res), f32x2 packed ----
__global__ __launch_bounds__(128) void k_inproj(
    const float* __restrict__ x, const float* __restrict__ Wg,
    const float* __restrict__ Wr, const float* __restrict__ br) {
    __shared__ float sx[8][64];
    int h = threadIdx.x;
    unsigned long long wp[64];
#pragma unroll
    for (int i = 0; i < 64; ++i) wp[i] = pack2(Wg[i * Hv + h], Wr[i * Hv + h]);
    float brh = br[h];
    int row0 = blockIdx.x * 128;
#pragma unroll 1
    for (int c = 0; c < 16; ++c) {
        int rbase = row0 + c * 8;
        __syncthreads();
        for (int j = h; j < 512; j += 128)
            sx[j >> 6][j & 63] = x[(rbase + (j >> 6)) * Fv + (j & 63)];
        __syncthreads();
#pragma unroll
        for (int r = 0; r < 8; ++r) {
            unsigned long long acc = 0ULL;
#pragma unroll
            for (int i = 0; i < 64; i += 4) {
                float4 xv = *(const float4*)&sx[r][i];
                fma2(acc, pack2(xv.x, xv.x), wp[i + 0]);
                fma2(acc, pack2(xv.y, xv.y), wp[i + 1]);
                fma2(acc, pack2(xv.z, xv.z), wp[i + 2]);
                fma2(acc, pack2(xv.w, xv.w), wp[i + 3]);
            }
            float ag, ar; unpack2(acc, ag, ar);
            int row = rbase + r;
            g_xf [row * Hv + h] = ag;
            g_res[row * Hv + h] = ar + brh;
        }
    }
}

// ---------------- K3: GCN aggregate + bias + gelu ----------------
__global__ __launch_bounds__(128) void k_gcn(const float* __restrict__ bg) {
    __shared__ float sxf[Nv * 16];
    int bt = blockIdx.x;
    int hbase = blockIdx.y * 16;
    int tid = threadIdx.x;
    const float* xsrc = g_xf + bt * (Nv * Hv);
    for (int idx = tid; idx < Nv * 16; idx += 128) {
        int n = idx >> 4, hh = idx & 15;
        sxf[idx] = xsrc[n * Hv + hbase + hh];
    }
    __syncthreads();
    int hh = tid & 15;
    int ns = tid >> 4;
    float bgv = bg[hbase + hh];
    float* dst = g_hg + bt * (Nv * Hv);
    for (int n = ns; n < Nv; n += 8) {
        int rs = g_rowptr[n], re = g_rowptr[n + 1];
        float acc = 0.0f;
        int e = rs;
        for (; e + 1 < re; e += 2) {
            float2 ev0 = g_ev[e];
            float2 ev1 = g_ev[e + 1];
            acc += ev0.x * sxf[__float_as_int(ev0.y) * 16 + hh];
            acc += ev1.x * sxf[__float_as_int(ev1.y) * 16 + hh];
        }
        if (e < re) {
            float2 ev0 = g_ev[e];
            acc += ev0.x * sxf[__float_as_int(ev0.y) * 16 + hh];
        }
        dst[n * Hv + hbase + hh] = gelu_exact(acc + bgv);
    }
}

// ============== K4: mma.sync bf16-split conv + gelu + res + LN ==============
// Block: M=128 rows (4 (b,n) pairs x 32 t), N=128 out-ch, K_eff=1152
// D = [Ah|Ah|Al] . [Bh|Bl|Bh]^T   (al*bl term dropped, ~2^-16)
#define AROWB   784                   // 24 ksteps * 32B + 16B pad
#define AL_OFF  100352                // 128 * 784
#define MU_OFF  200704
#define RS_OFF  201216
#define CONV_SMEM 201728

__global__ __launch_bounds__(256, 1) void k_conv_mma(
    const float* __restrict__ btmp, const float* __restrict__ lnw,
    const float* __restrict__ lnb, float* __restrict__ out) {
    extern __shared__ __align__(16) char smc[];
    uint32_t sb = smem_u32(smc);
    int tid = threadIdx.x;
    int lane = tid & 31, w = tid >> 5;
    int mrow0 = (w & 3) * 32;
    int nwarp = w >> 2;

    // ---- stage A (hi & lo) into smem ----
    {
        int row = tid & 127, ih = tid >> 7;
        int p = row >> 5, t = row & 31;
        int bn = blockIdx.x * 4 + p;
        int b = bn / Nv, n = bn % Nv;
#pragma unroll
        for (int kk = 0; kk < 3; ++kk) {
            int tin = t + kk - 1;
            bool valid = (tin >= 0 && tin < Tv);
            const float4* src = (const float4*)(g_hg +
                ((size_t)((b * Tv + (valid ? tin : 0)) * Nv + n)) * Hv + ih * 64);
            uint32_t off = (uint32_t)row * AROWB + kk * 256 + ih * 128;
#pragma unroll
            for (int c4 = 0; c4 < 16; ++c4) {
                float4 v = valid ? src[c4] : make_float4(0.f, 0.f, 0.f, 0.f);
                uint32_t h0, l0, h1, l1;
                split2(v.x, v.y, h0, l0);
                split2(v.z, v.w, h1, l1);
                *(uint32_t*)(smc + off + c4 * 8)              = h0;
                *(uint32_t*)(smc + off + c4 * 8 + 4)          = h1;
                *(uint32_t*)(smc + AL_OFF + off + c4 * 8)     = l0;
                *(uint32_t*)(smc + AL_OFF + off + c4 * 8 + 4) = l1;
            }
        }
    }
    __syncthreads();

    // ---- mainloop: 72 k16-steps ----
    float d[2][8][4];
#pragma unroll
    for (int mi = 0; mi < 2; ++mi)
#pragma unroll
        for (int ni = 0; ni < 8; ++ni)
#pragma unroll
            for (int r = 0; r < 4; ++r) d[mi][ni][r] = 0.0f;

    uint2 bfr[2][8];
    {   // preload b for s=0 (sel=h, q=0)
        const uint2* bp = g_wfrag + (0 * 16 + nwarp * 8) * 32 + lane;
#pragma unroll
        for (int ni = 0; ni < 8; ++ni) bfr[0][ni] = bp[ni * 32];
    }
    uint32_t arowoff = (uint32_t)(mrow0 + (lane & 15)) * AROWB + ((lane >> 4) << 4);

#pragma unroll 2
    for (int s = 0; s < 72; ++s) {
        int q = s % 24;
        uint32_t abase = sb + ((s < 48) ? 0u : (uint32_t)AL_OFF) + q * 32 + arowoff;
        uint32_t a0[4], a1[4];
        ldmx4(a0, abase);
        ldmx4(a1, abase + 16 * AROWB);
        if (s + 1 < 72) {
            int s1 = s + 1;
            int q1 = s1 % 24;
            int sel = (s1 >= 24 && s1 < 48) ? 1 : 0;
            const uint2* bp = g_wfrag + ((sel * 24 + q1) * 16 + nwarp * 8) * 32 + lane;
#pragma unroll
            for (int ni = 0; ni < 8; ++ni) bfr[(s1) & 1][ni] = bp[ni * 32];
        }
#pragma unroll
        for (int ni = 0; ni < 8; ++ni) {
            mma16816(d[0][ni], a0, bfr[s & 1][ni]);
            mma16816(d[1][ni], a1, bfr[s & 1][ni]);
        }
    }
    __syncthreads();   // all warps done reading A; reuse smem as y[128][129] f32

    // ---- frag epilogue: y = gelu(d + bias) + res ----
    {
        int p = w & 3;
        int bn = blockIdx.x * 4 + p;
        int b = bn / Nv, n = bn % Nv;
        float* y = (float*)smc;
#pragma unroll
        for (int mi = 0; mi < 2; ++mi) {
            int r1 = mrow0 + mi * 16 + (lane >> 2);
            int t1 = r1 & 31;
            size_t g1 = ((size_t)((b * Tv + t1) * Nv + n)) * Hv;
            size_t g2 = ((size_t)((b * Tv + t1 + 8) * Nv + n)) * Hv;
#pragma unroll
            for (int ni = 0; ni < 8; ++ni) {
                int c = nwarp * 64 + ni * 8 + (lane & 3) * 2;
                float2 rs1 = *(const float2*)(g_res + g1 + c);
                float2 rs2 = *(const float2*)(g_res + g2 + c);
                float bb0 = __ldg(btmp + c), bb1 = __ldg(btmp + c + 1);
                y[r1 * 129 + c]           = gelu_exact(d[mi][ni][0] + bb0) + rs1.x;
                y[r1 * 129 + c + 1]       = gelu_exact(d[mi][ni][1] + bb1) + rs1.y;
                y[(r1 + 8) * 129 + c]     = gelu_exact(d[mi][ni][2] + bb0) + rs2.x;
                y[(r1 + 8) * 129 + c + 1] = gelu_exact(d[mi][ni][3] + bb1) + rs2.y;
            }
        }
    }
    __syncthreads();

    // ---- per-row LayerNorm stats ----
    if (tid < 128) {
        const float* y = (const float*)smc;
        int r = tid;
        float s1 = 0.0f;
#pragma unroll 8
        for (int j = 0; j < 128; ++j) s1 += y[r * 129 + j];
        float mu = s1 * (1.0f / 128.0f);
        float s2 = 0.0f;
#pragma unroll 8
        for (int j = 0; j < 128; ++j) {
            float dd = y[r * 129 + j] - mu;
            s2 += dd * dd;
        }
        ((float*)(smc + MU_OFF))[r] = mu;
        ((float*)(smc + RS_OFF))[r] = rsqrtf(s2 * (1.0f / 128.0f) + 1e-5f);
    }
    __syncthreads();

    // ---- normalize + store ----
    {
        const float* y = (const float*)smc;
        int row = tid >> 1, ch = (tid & 1) * 64;
        int p = row >> 5, t = row & 31;
        int bn = blockIdx.x * 4 + p;
        int b = bn / Nv, n = bn % Nv;
        float mu = ((const float*)(smc + MU_OFF))[row];
        float rs = ((const float*)(smc + RS_OFF))[row];
        float4* op = (float4*)(out + ((size_t)((b * Tv + t) * Nv + n)) * Hv + ch);
        const float4* lw4 = (const float4*)(lnw + ch);
        const float4* lb4 = (const float4*)(lnb + ch);
#pragma unroll
        for (int c4 = 0; c4 < 16; ++c4) {
            float4 wv = lw4[c4];
            float4 bv = lb4[c4];
            const float* yp = y + row * 129 + ch + c4 * 4;
            float4 ov;
            ov.x = (yp[0] - mu) * rs * wv.x + bv.x;
            ov.y = (yp[1] - mu) * rs * wv.y + bv.y;
            ov.z = (yp[2] - mu) * rs * wv.z + bv.z;
            ov.w = (yp[3] - mu) * rs * wv.w + bv.w;
            op[c4] = ov;
        }
    }
}

// ---------------- launch ----------------
extern "C" void kernel_launch(void* const* d_in, const int* in_sizes, int n_in,
                              void* d_out, int out_size) {
    const float* x   = (const float*)d_in[0];
    const void*  ei  = d_in[1];
    const float* ew  = (const float*)d_in[2];
    const float* Wg  = (const float*)d_in[3];
    const float* bg  = (const float*)d_in[4];
    const float* Wt  = (const float*)d_in[5];
    const float* btm = (const float*)d_in[6];
    const float* lnw = (const float*)d_in[7];
    const float* lnb = (const float*)d_in[8];
    const float* Wr  = (const float*)d_in[9];
    const float* br  = (const float*)d_in[10];
    float* out = (float*)d_out;

    cudaFuncSetAttribute(k_conv_mma, cudaFuncAttributeMaxDynamicSharedMemorySize,
                         CONV_SMEM);

    p_detect<<<1, 32>>>(ei);
    p_init<<<1, 512>>>();
    p_deg <<<(Ev + 127) / 128, 128>>>(ei, ew);
    p_scan<<<1, 512>>>();
    p_fill<<<(NNZ + 127) / 128, 128>>>(ei, ew);
    p_wsplit<<<96, 128>>>(Wt);
    k_inproj<<<1000, 128>>>(x, Wg, Wr, br);
    k_gcn<<<dim3(BT, 8), 128>>>(bg);
    k_conv_mma<<<1000, 256, CONV_SMEM>>>(btm, lnw, lnb, out);
}